// round 15
// baseline (speedup 1.0000x reference)
#include <cuda_runtime.h>
#include <cuda_fp16.h>
#include <math.h>
#include <stdint.h>

// Problem constants
#define BB 32
#define TT 2048
#define PP 128
#define KK 256
#define MM 64
#define CCH 410            // independent 5-step chunks
#define NR (BB*CCH)        // 13120 state rows
#define NRP 13184          // NR padded to 128 multiple
#define NROWS (BB*TT)      // 65536 encoder rows

// fp16 weight pack offsets (in halfs)
#define W_EX1 0
#define W_EX2 32768
#define W_EX3 98304
#define W_EZ1 163840
#define W_EZ2 172032
#define W_EZ3 176128
#define W_DE1 180224
#define W_DE2 245760
#define W_TOTAL 278528

// fp32 step-weight pack offsets (floats)
#define P_WZT 0        // 64x64 transposed
#define P_AZT 4096     // 8x68 row-major (pitch 68)
#define P_L   4640     // 256x12 (pitch 12)
#define P_RT  7712     // 8x256 transposed
#define P_AZB 9760     // 8
#define P_TOT 9768

// Scratch (device globals; zero-initialized)
__device__ __half g_w16[W_TOTAL];
__device__ float  g_step[P_TOT];
__device__ float  g_X[NRP*KK];                  // fp32 scan-state init; pad rows 0
__device__ float  g_Z[NR*MM];
__device__ __half g_X16s[(size_t)5*NRP*KK];     // per-step x snapshots; pad rows 0

// ---------------------------------------------------------------------------
// helpers
// ---------------------------------------------------------------------------
__device__ __forceinline__ void cpa16(uint32_t dst, const void* src) {
    asm volatile("cp.async.cg.shared.global [%0], [%1], 16;\n"
                 :: "r"(dst), "l"(src));
}
__device__ __forceinline__ void commitg() {
    asm volatile("cp.async.commit_group;\n" ::: "memory");
}
template<int N> __device__ __forceinline__ void waitg() {
    asm volatile("cp.async.wait_group %0;\n" :: "n"(N) : "memory");
}
__device__ __forceinline__ void ldsm4(uint32_t* r, uint32_t addr) {
    asm volatile("ldmatrix.sync.aligned.m8n8.x4.shared.b16 {%0,%1,%2,%3}, [%4];\n"
        : "=r"(r[0]), "=r"(r[1]), "=r"(r[2]), "=r"(r[3]) : "r"(addr));
}
__device__ __forceinline__ void mma16816(float* c, const uint32_t* a,
                                         uint32_t b0, uint32_t b1) {
    asm volatile(
      "mma.sync.aligned.m16n8k16.row.col.f32.f16.f16.f32 "
      "{%0,%1,%2,%3}, {%4,%5,%6,%7}, {%8,%9}, {%0,%1,%2,%3};\n"
      : "+f"(c[0]), "+f"(c[1]), "+f"(c[2]), "+f"(c[3])
      : "r"(a[0]), "r"(a[1]), "r"(a[2]), "r"(a[3]), "r"(b0), "r"(b1));
}
// accurate fast tanh (abs err ~1e-7): all output-facing tanh
__device__ __forceinline__ float ftanh(float x) {
    float e = __expf(2.0f * x);
    return 1.0f - __fdividef(2.0f, e + 1.0f);
}
// hardware tanh approx: recurrence-internal only (error attenuated by /100)
__device__ __forceinline__ float htanh(float x) {
    float y; asm("tanh.approx.f32 %0, %1;" : "=f"(y) : "f"(x)); return y;
}

// ---------------------------------------------------------------------------
// One-time conversion: weights -> fp16; step weights -> packed fp32
// ---------------------------------------------------------------------------
__global__ void conv_kernel(const float* __restrict__ ex1, const float* __restrict__ ex2,
                            const float* __restrict__ ex3, const float* __restrict__ ez1,
                            const float* __restrict__ ez2, const float* __restrict__ ez3,
                            const float* __restrict__ de1, const float* __restrict__ de2,
                            const float* __restrict__ Wz,  const float* __restrict__ Azw,
                            const float* __restrict__ Azb, const float* __restrict__ Lw,
                            const float* __restrict__ Rm)
{
    int i4 = blockIdx.x * blockDim.x + threadIdx.x;
    int j = i4 * 4;
    if (j < W_TOTAL) {
        const float* src; int off;
        if      (j < W_EX2) { src = ex1; off = W_EX1; }
        else if (j < W_EX3) { src = ex2; off = W_EX2; }
        else if (j < W_EZ1) { src = ex3; off = W_EX3; }
        else if (j < W_EZ2) { src = ez1; off = W_EZ1; }
        else if (j < W_EZ3) { src = ez2; off = W_EZ2; }
        else if (j < W_DE1) { src = ez3; off = W_EZ3; }
        else if (j < W_DE2) { src = de1; off = W_DE1; }
        else                { src = de2; off = W_DE2; }
        float4 v = reinterpret_cast<const float4*>(src)[(j - off) >> 2];
        __half2 a = __floats2half2_rn(v.x, v.y), b = __floats2half2_rn(v.z, v.w);
        uint2 u = { *reinterpret_cast<unsigned*>(&a), *reinterpret_cast<unsigned*>(&b) };
        *reinterpret_cast<uint2*>(&g_w16[j]) = u;
        return;
    }
    int sidx = i4 - W_TOTAL/4;
    if (sidx >= P_TOT) return;
    float v;
    if (sidx < P_AZT) {
        v = Wz[(sidx & 63)*64 + (sidx >> 6)];
    } else if (sidx < P_L) {
        int q = sidx - P_AZT;
        int row = q / 68, col = q % 68;
        v = (col < 64) ? Azw[row*64 + col] : 0.f;
    } else if (sidx < P_RT) {
        int q = sidx - P_L;
        int row = q / 12, col = q % 12;
        v = (col < 8) ? Lw[row*8 + col] : 0.f;
    } else if (sidx < P_AZB) {
        int q = sidx - P_RT;
        v = Rm[(q & 255)*8 + (q >> 8)];
    } else {
        v = Azb[sidx - P_AZB];
    }
    g_step[sidx] = v;
}

// ---------------------------------------------------------------------------
// Issue one BKT-wide weight stage (Nd rows x BKT halfs) of layer gW (row
// stride Kd) into ring slot `slot` (slot stride 256 x 136 halfs).
// ---------------------------------------------------------------------------
template<int THREADS, int Nd, int Kd, int BKT>
__device__ __forceinline__ void issueB(const __half* __restrict__ gW, int t,
                                       int slot, uint32_t bBase)
{
    constexpr int CPR = BKT / 8;
    constexpr int CH = Nd * CPR;
    const int tid = threadIdx.x;
    #pragma unroll
    for (int c = tid; c < CH; c += THREADS) {
        int row = c / CPR, off = (c % CPR) * 8;
        cpa16(bBase + (uint32_t)(((slot * 256 + row) * 136 + off) * 2),
              gW + (size_t)row * Kd + t * BKT + off);
    }
}

// ---------------------------------------------------------------------------
// gemm2: acc(128 x Nd) += sA(128 x Kd, pitch Kd+8) @ gW(Nd x Kd)^T
// BKT = min(Kd,128) stages; 2-slot ring (slot stride 256x136 halfs); global
// depth-1 stream: at stage s top waitg<0>+sync, then issue global stage s+1
// (own, or chain() = successor layers' stage 0), commit, compute slot
// (SBASE+s)&1.  Entry invariant: this layer's stage 0 is the newest commit
// group; slot parity = SBASE.
// ---------------------------------------------------------------------------
template<int THREADS, int Nd, int Kd, int NT, int SBASE, typename F>
__device__ __forceinline__ void gemm2(const __half* __restrict__ gW,
                                      const __half* sA, __half* sB,
                                      float (&acc)[2][NT][4], F&& chain)
{
    constexpr int BKT = (Kd < 128) ? Kd : 128;
    constexpr int BP = 136, AP = Kd + 8;
    constexpr int S = Kd / BKT;
    constexpr int NWN = THREADS / 128;
    constexpr int WN = Nd / NWN;
    static_assert(NT == WN / 8, "NT mismatch");

    const int tid = threadIdx.x, lane = tid & 31, wid = tid >> 5;
    const int wm = wid & 3, wn = wid >> 2;
    const uint32_t aBase = (uint32_t)__cvta_generic_to_shared(sA);
    const uint32_t bBase = (uint32_t)__cvta_generic_to_shared(sB);
    const int arow = wm * 32 + (lane & 15);
    const int akof = (lane >> 4) << 3;
    const int brow = wn * WN + (lane & 7) + ((lane >> 4) << 3);
    const int bkof = ((lane >> 3) & 1) << 3;

    #pragma unroll
    for (int i = 0; i < 2; i++)
        #pragma unroll
        for (int j = 0; j < NT; j++)
            #pragma unroll
            for (int q = 0; q < 4; q++) acc[i][j][q] = 0.f;

    #pragma unroll
    for (int s = 0; s < S; s++) {
        waitg<0>();
        __syncthreads();
        if (s + 1 < S) issueB<THREADS, Nd, Kd, BKT>(gW, s + 1, (SBASE + s + 1) & 1, bBase);
        else           chain(0);
        commitg();
        const int slot = (SBASE + s) & 1;
        #pragma unroll
        for (int kk = 0; kk < BKT; kk += 16) {
            uint32_t af[2][4];
            uint32_t aa = aBase + (uint32_t)((arow * AP + s * BKT + kk + akof) * 2);
            ldsm4(af[0], aa);
            ldsm4(af[1], aa + 16 * AP * 2);
            #pragma unroll
            for (int j2 = 0; j2 < NT / 2; j2++) {
                uint32_t bf[4];
                ldsm4(bf, bBase + (uint32_t)(((slot * 256 + brow + j2 * 16) * BP + kk + bkof) * 2));
                mma16816(acc[0][2 * j2],     af[0], bf[0], bf[1]);
                mma16816(acc[0][2 * j2 + 1], af[0], bf[2], bf[3]);
                mma16816(acc[1][2 * j2],     af[1], bf[0], bf[1]);
                mma16816(acc[1][2 * j2 + 1], af[1], bf[2], bf[3]);
            }
        }
    }
}

// ---------------------------------------------------------------------------
// Epilogue: ftanh(acc + bias) -> pitched smem (pitch Nd + 8)
// ---------------------------------------------------------------------------
template<int THREADS, int Nd, int NT>
__device__ __forceinline__ void epi_to_smem(float (&acc)[2][NT][4],
        const float* __restrict__ bias, __half* sOut)
{
    constexpr int NWN = THREADS / 128, WN = Nd / NWN, OP = Nd + 8;
    const int tid = threadIdx.x, lane = tid & 31, wid = tid >> 5;
    const int wm = wid & 3, wn = wid >> 2;
    const int g = lane >> 2, cq = (lane & 3) << 1;
    #pragma unroll
    for (int i = 0; i < 2; i++)
        #pragma unroll
        for (int h = 0; h < 2; h++) {
            const int row = wm * 32 + i * 16 + h * 8 + g;
            #pragma unroll
            for (int nt = 0; nt < NT; nt++) {
                const int col = wn * WN + nt * 8 + cq;
                float v0 = ftanh(acc[i][nt][2 * h + 0] + __ldg(bias + col));
                float v1 = ftanh(acc[i][nt][2 * h + 1] + __ldg(bias + col + 1));
                *reinterpret_cast<__half2*>(sOut + row * OP + col) =
                    __floats2half2_rn(v0, v1);
            }
        }
}

// ---------------------------------------------------------------------------
// fused_xz (512 thr): BK=128 2-slot ring; in-place A; single in-place zQ
// buffer living in the in16 slack (in16 tile = 128x136 halfs of sA).
// Order: ez1 -> ez2 -> ez3 (z_seq + Z init) -> ex1 -> ex2 -> ex3 (X init)
//        -> de1 -> de2 -> x_rec.
// Global stages: ez1[G0] ez2[G1] ez3[G2] ex1[G3] ex2[G4,5] ex3[G6,7]
//                de1[G8,9] de2[G10,11];  slot = G & 1.
// smem halfs: sA 33792 | sB 2*256*136 = 69632    (206848 B total)
// ---------------------------------------------------------------------------
__global__ void __launch_bounds__(512, 1)
fused_xz(const float* __restrict__ in_seq,
         const float* __restrict__ bx1, const float* __restrict__ bx2,
         const float* __restrict__ bx3, const float* __restrict__ bz1,
         const float* __restrict__ bz2, const float* __restrict__ bz3,
         const float* __restrict__ bd1, const float* __restrict__ bd2,
         float* __restrict__ x_rec, float* __restrict__ z_seq)
{
    extern __shared__ __half sm[];
    __half* sA = sm;                   // 33792 halfs
    __half* zQ = sm + 17408;           // 9216 halfs (128x72), in16 slack
    __half* sB = sm + 33792;           // 69632 halfs
    const uint32_t bB = (uint32_t)__cvta_generic_to_shared(sB);
    const int row0 = blockIdx.x * 128;
    const int tid = threadIdx.x, lane = tid & 31, wid = tid >> 5;
    const int wm = wid & 3, wn = wid >> 2;
    const int g = lane >> 2, cq = (lane & 3) << 1;

    // prefill: ez1 stage0 -> slot0
    issueB<512, 64, 128, 128>(g_w16 + W_EZ1, 0, 0, bB); commitg();

    // direct in_seq fp32 -> fp16 tile (pitch 136) in sA (covers stage0 latency)
    #pragma unroll
    for (int c = tid; c < 128 * 32; c += 512) {
        int row = c >> 5, off = (c & 31) << 2;
        float4 v = *reinterpret_cast<const float4*>(
            in_seq + (size_t)(row0 + row) * PP + off);
        __half2 a = __floats2half2_rn(v.x, v.y), b = __floats2half2_rn(v.z, v.w);
        uint2 u = { *reinterpret_cast<unsigned*>(&a), *reinterpret_cast<unsigned*>(&b) };
        *reinterpret_cast<uint2*>(&sA[row * 136 + off]) = u;
    }

    // ez1 (in16 -> zQ); chains ez2 s0 -> slot1
    {   float acc[2][2][4];
        gemm2<512, 64, 128, 2, 0>(g_w16 + W_EZ1, sA, sB, acc, [&](int){
            issueB<512, 64, 64, 64>(g_w16 + W_EZ2, 0, 1, bB);
        });
        epi_to_smem<512, 64, 2>(acc, bz1, zQ);
    }
    // ez2 (zQ -> in-place zQ); chains ez3 s0 -> slot0
    {   float acc[2][2][4];
        gemm2<512, 64, 64, 2, 1>(g_w16 + W_EZ2, zQ, sB, acc, [&](int){
            issueB<512, 64, 64, 64>(g_w16 + W_EZ3, 0, 0, bB);
        });
        __syncthreads();                  // all reads of zQ done before rewrite
        epi_to_smem<512, 64, 2>(acc, bz2, zQ);
    }
    // ez3 -> z_seq fp32 + Z init; chains ex1 s0 -> slot1
    {   float acc[2][2][4];
        gemm2<512, 64, 64, 2, 0>(g_w16 + W_EZ3, zQ, sB, acc, [&](int){
            issueB<512, 256, 128, 128>(g_w16 + W_EX1, 0, 1, bB);
        });
        #pragma unroll
        for (int i = 0; i < 2; i++)
            #pragma unroll
            for (int h = 0; h < 2; h++) {
                const int row = wm * 32 + i * 16 + h * 8 + g;
                const int r = row0 + row;
                const int t = r & (TT - 1);
                const int rs = (t % 5 == 0) ? ((r >> 11) * CCH + t / 5) : -1;
                #pragma unroll
                for (int nt = 0; nt < 2; nt++) {
                    const int col = wn * 16 + nt * 8 + cq;
                    float v0 = ftanh(acc[i][nt][2 * h + 0] + __ldg(bz3 + col));
                    float v1 = ftanh(acc[i][nt][2 * h + 1] + __ldg(bz3 + col + 1));
                    *reinterpret_cast<float2*>(z_seq + (size_t)r * MM + col) =
                        make_float2(v0, v1);
                    if (rs >= 0)
                        *reinterpret_cast<float2*>(&g_Z[(size_t)rs * MM + col]) =
                            make_float2(v0, v1);
                }
            }
    }
    // ex1 (in16 -> in-place sA); chains ex2 s0 -> slot0
    {   float acc[2][8][4];
        gemm2<512, 256, 128, 8, 1>(g_w16 + W_EX1, sA, sB, acc, [&](int){
            issueB<512, 256, 256, 128>(g_w16 + W_EX2, 0, 0, bB);
        });
        __syncthreads();
        epi_to_smem<512, 256, 8>(acc, bx1, sA);
    }
    // ex2 (sA -> sA); chains ex3 s0 -> slot0
    {   float acc[2][8][4];
        gemm2<512, 256, 256, 8, 0>(g_w16 + W_EX2, sA, sB, acc, [&](int){
            issueB<512, 256, 256, 128>(g_w16 + W_EX3, 0, 0, bB);
        });
        __syncthreads();
        epi_to_smem<512, 256, 8>(acc, bx2, sA);
    }
    // ex3 (sA -> sA) + fp32 X init; chains de1 s0 -> slot0
    {   float acc[2][8][4];
        gemm2<512, 256, 256, 8, 0>(g_w16 + W_EX3, sA, sB, acc, [&](int){
            issueB<512, 256, 256, 128>(g_w16 + W_DE1, 0, 0, bB);
        });
        __syncthreads();
        #pragma unroll
        for (int i = 0; i < 2; i++)
            #pragma unroll
            for (int h = 0; h < 2; h++) {
                const int row = wm * 32 + i * 16 + h * 8 + g;
                const int r = row0 + row;
                const int t = r & (TT - 1);
                const int rs = (t % 5 == 0) ? ((r >> 11) * CCH + t / 5) : -1;
                #pragma unroll
                for (int nt = 0; nt < 8; nt++) {
                    const int col = wn * 64 + nt * 8 + cq;
                    float v0 = ftanh(acc[i][nt][2 * h + 0] + __ldg(bx3 + col));
                    float v1 = ftanh(acc[i][nt][2 * h + 1] + __ldg(bx3 + col + 1));
                    *reinterpret_cast<__half2*>(sA + row * 264 + col) =
                        __floats2half2_rn(v0, v1);
                    if (rs >= 0)
                        *reinterpret_cast<float2*>(&g_X[(size_t)rs * KK + col]) =
                            make_float2(v0, v1);
                }
            }
    }
    // de1 (sA -> sA); chains de2 s0 -> slot0
    {   float acc[2][8][4];
        gemm2<512, 256, 256, 8, 0>(g_w16 + W_DE1, sA, sB, acc, [&](int){
            issueB<512, 128, 256, 128>(g_w16 + W_DE2, 0, 0, bB);
        });
        __syncthreads();
        epi_to_smem<512, 256, 8>(acc, bd1, sA);
    }
    // de2 -> x_rec (fp32 dense)
    {   float acc[2][4][4];
        gemm2<512, 128, 256, 4, 0>(g_w16 + W_DE2, sA, sB, acc, [](int){});
        #pragma unroll
        for (int i = 0; i < 2; i++)
            #pragma unroll
            for (int h = 0; h < 2; h++) {
                const int row = wm * 32 + i * 16 + h * 8 + g;
                const int r = row0 + row;
                #pragma unroll
                for (int nt = 0; nt < 4; nt++) {
                    const int col = wn * 32 + nt * 8 + cq;
                    float v0 = ftanh(acc[i][nt][2 * h + 0] + __ldg(bd2 + col));
                    float v1 = ftanh(acc[i][nt][2 * h + 1] + __ldg(bd2 + col + 1));
                    *reinterpret_cast<float2*>(x_rec + (size_t)r * PP + col) =
                        make_float2(v0, v1);
                }
            }
    }
}

// ---------------------------------------------------------------------------
// mega_step (R11 version): all 5 recurrence sub-steps; 4 rows per warp,
// state in registers; conflict-free gate reads (Az pitch 68).
// ---------------------------------------------------------------------------
__global__ void __launch_bounds__(256, 2)
mega_step(float* __restrict__ zpred)
{
    __shared__ __align__(16) float sP[P_TOT];
    __shared__ __align__(16) float stz[8][4][68];

    const int tid = threadIdx.x;
    for (int i = tid; i < P_TOT; i += 256) sP[i] = g_step[i];
    __syncthreads();
    const float*  sWzT = sP + P_WZT;
    const float*  sAzQ = sP + P_AZT;
    const float4* sL4  = (const float4*)(sP + P_L);
    const float*  sRT  = sP + P_RT;
    const float*  sAzb = sP + P_AZB;

    const int w = tid >> 5, lane = tid & 31;
    const int r0 = (blockIdx.x * 8 + w) * 4;
    const int gr = lane >> 3, gq = lane & 7;

    int tbase[4]; size_t zoff[4];
    float zv0[4], zv1[4], xv[4][8];
    #pragma unroll
    for (int r = 0; r < 4; r++) {
        const int rr = r0 + r;
        const int b = rr / CCH, c = rr % CCH;
        tbase[r] = 5 * c;
        zoff[r]  = ((size_t)b * TT) * MM;
        zv0[r] = g_Z[(size_t)rr * MM + lane];
        zv1[r] = g_Z[(size_t)rr * MM + 32 + lane];
        #pragma unroll
        for (int k = 0; k < 8; k++)
            xv[r][k] = g_X[(size_t)rr * KK + lane + 32 * k];
    }

    #pragma unroll 1
    for (int s = 0; s < 5; s++) {
        #pragma unroll
        for (int r = 0; r < 4; r++) {
            stz[w][r][lane]      = htanh(zv0[r]);
            stz[w][r][lane + 32] = htanh(zv1[r]);
        }
        __syncwarp();
        float a0[4] = {0.f,0.f,0.f,0.f}, a1[4] = {0.f,0.f,0.f,0.f};
        #pragma unroll
        for (int i4 = 0; i4 < 16; i4++) {
            float4 tz[4];
            #pragma unroll
            for (int r = 0; r < 4; r++)
                tz[r] = *(const float4*)&stz[w][r][i4 * 4];
            const float* wr = sWzT + (i4 * 4) * 64 + lane;
            #pragma unroll
            for (int ii = 0; ii < 4; ii++) {
                const float w0 = wr[ii * 64], w1 = wr[ii * 64 + 32];
                const float c0 = (ii == 0) ? tz[0].x : (ii == 1) ? tz[0].y
                               : (ii == 2) ? tz[0].z : tz[0].w;
                const float c1 = (ii == 0) ? tz[1].x : (ii == 1) ? tz[1].y
                               : (ii == 2) ? tz[1].z : tz[1].w;
                const float c2 = (ii == 0) ? tz[2].x : (ii == 1) ? tz[2].y
                               : (ii == 2) ? tz[2].z : tz[2].w;
                const float c3 = (ii == 0) ? tz[3].x : (ii == 1) ? tz[3].y
                               : (ii == 2) ? tz[3].z : tz[3].w;
                a0[0] = fmaf(c0, w0, a0[0]);  a1[0] = fmaf(c0, w1, a1[0]);
                a0[1] = fmaf(c1, w0, a0[1]);  a1[1] = fmaf(c1, w1, a1[1]);
                a0[2] = fmaf(c2, w0, a0[2]);  a1[2] = fmaf(c2, w1, a1[2]);
                a0[3] = fmaf(c3, w0, a0[3]);  a1[3] = fmaf(c3, w1, a1[3]);
            }
        }
        #pragma unroll
        for (int r = 0; r < 4; r++) {
            zv0[r] = zv0[r] + (a0[r] - zv0[r]) * 0.01f;
            zv1[r] = zv1[r] + (a1[r] - zv1[r]) * 0.01f;
        }
        __syncwarp();
        #pragma unroll
        for (int r = 0; r < 4; r++) {
            stz[w][r][lane]      = zv0[r];
            stz[w][r][lane + 32] = zv1[r];
        }
        __syncwarp();
        float ga = 0.f;
        {
            const float4* az4 = (const float4*)(sAzQ + gq * 68);
            const float4* zz4 = (const float4*)&stz[w][gr][0];
            #pragma unroll
            for (int i4 = 0; i4 < 16; i4++) {
                float4 a = az4[i4], z = zz4[i4];
                ga = fmaf(z.x, a.x, ga);
                ga = fmaf(z.y, a.y, ga);
                ga = fmaf(z.z, a.z, ga);
                ga = fmaf(z.w, a.w, ga);
            }
        }
        const float sg = 1.f / (1.f + __expf(-(ga + sAzb[gq])));
        float gu[4][8];
        #pragma unroll
        for (int r = 0; r < 4; r++)
            #pragma unroll
            for (int q = 0; q < 8; q++) gu[r][q] = 0.f;
        #pragma unroll
        for (int k = 0; k < 8; k++) {
            const int j = lane + 32 * k;
            const float4 l0 = sL4[j * 3], l1 = sL4[j * 3 + 1];
            #pragma unroll
            for (int r = 0; r < 4; r++) {
                const float tx = htanh(xv[r][k]);
                gu[r][0] = fmaf(tx, l0.x, gu[r][0]);
                gu[r][1] = fmaf(tx, l0.y, gu[r][1]);
                gu[r][2] = fmaf(tx, l0.z, gu[r][2]);
                gu[r][3] = fmaf(tx, l0.w, gu[r][3]);
                gu[r][4] = fmaf(tx, l1.x, gu[r][4]);
                gu[r][5] = fmaf(tx, l1.y, gu[r][5]);
                gu[r][6] = fmaf(tx, l1.z, gu[r][6]);
                gu[r][7] = fmaf(tx, l1.w, gu[r][7]);
            }
        }
        #pragma unroll
        for (int off = 16; off > 0; off >>= 1)
            #pragma unroll
            for (int r = 0; r < 4; r++)
                #pragma unroll
                for (int q = 0; q < 8; q++)
                    gu[r][q] += __shfl_xor_sync(0xffffffffu, gu[r][q], off);
        #pragma unroll
        for (int r = 0; r < 4; r++)
            #pragma unroll
            for (int q = 0; q < 8; q++)
                gu[r][q] *= __shfl_sync(0xffffffffu, sg, r * 8 + q);
        #pragma unroll
        for (int k = 0; k < 8; k++) {
            const int j = lane + 32 * k;
            float acc[4] = {0.f,0.f,0.f,0.f};
            #pragma unroll
            for (int q = 0; q < 8; q++) {
                const float wv = sRT[q * 256 + j];
                acc[0] = fmaf(gu[0][q], wv, acc[0]);
                acc[1] = fmaf(gu[1][q], wv, acc[1]);
                acc[2] = fmaf(gu[2][q], wv, acc[2]);
                acc[3] = fmaf(gu[3][q], wv, acc[3]);
            }
            #pragma unroll
            for (int r = 0; r < 4; r++)
                xv[r][k] = xv[r][k] + (acc[r] - xv[r][k]) * 0.01f;
        }
        #pragma unroll
        for (int r = 0; r < 4; r++) {
            const int t = tbase[r] + s;
            if (t < TT) {
                float* zp = zpred + zoff[r] + (size_t)t * MM;
                zp[lane]      = zv0[r];
                zp[lane + 32] = zv1[r];
            }
            __half* xd = g_X16s + ((size_t)s * NRP + (r0 + r)) * KK;
            #pragma unroll
            for (int k = 0; k < 8; k++)
                xd[lane + 32 * k] = __float2half(xv[r][k]);
        }
    }
}

// ---------------------------------------------------------------------------
// fused_dec (512 thr): X16s -> de1 -> de2 -> x_pred; BK=128 2-slot ring.
// Global stages: de1[G0,1] de2[G2,3]; slot = G & 1.
// smem halfs: sA 33792 | sB 69632   (206848 B)
// ---------------------------------------------------------------------------
__global__ void __launch_bounds__(512, 1)
fused_dec(const float* __restrict__ bd1, const float* __restrict__ bd2,
          float* __restrict__ x_pred)
{
    extern __shared__ __half sm[];
    __half* sA = sm;
    __half* sB = sm + 33792;
    const uint32_t bB = (uint32_t)__cvta_generic_to_shared(sB);
    const int s    = blockIdx.x / (NRP / 128);
    const int row0 = (blockIdx.x % (NRP / 128)) * 128;
    const int tid = threadIdx.x, lane = tid & 31, wid = tid >> 5;
    const int wm = wid & 3, wn = wid >> 2;
    const int g = lane >> 2, cq = (lane & 3) << 1;

    // A tile + de1 stage0 (slot0), one combined drain at gemm entry
    {
        const __half* gA = g_X16s + ((size_t)s * NRP + row0) * KK;
        uint32_t d = (uint32_t)__cvta_generic_to_shared(sA);
        #pragma unroll
        for (int c = tid; c < 128 * 32; c += 512) {
            int row = c >> 5, off = (c & 31) << 3;
            cpa16(d + (uint32_t)((row * 264 + off) * 2), gA + (size_t)row * KK + off);
        }
        commitg();
        issueB<512, 256, 256, 128>(g_w16 + W_DE1, 0, 0, bB); commitg();
    }

    // de1; chains de2 s0 -> slot0
    {   float acc[2][8][4];
        gemm2<512, 256, 256, 8, 0>(g_w16 + W_DE1, sA, sB, acc, [&](int){
            issueB<512, 128, 256, 128>(g_w16 + W_DE2, 0, 0, bB);
        });
        __syncthreads();
        epi_to_smem<512, 256, 8>(acc, bd1, sA);
    }
    // de2 -> scatter x_pred
    {   float acc[2][4][4];
        gemm2<512, 128, 256, 4, 0>(g_w16 + W_DE2, sA, sB, acc, [](int){});
        #pragma unroll
        for (int i = 0; i < 2; i++)
            #pragma unroll
            for (int h = 0; h < 2; h++) {
                const int row = wm * 32 + i * 16 + h * 8 + g;
                const int r = row0 + row;
                if (r >= NR) continue;
                const int b = r / CCH, c = r % CCH;
                const int t = 5 * c + s;
                if (t >= TT) continue;
                float* crow = x_pred + ((size_t)b * TT + t) * PP;
                #pragma unroll
                for (int nt = 0; nt < 4; nt++) {
                    const int col = wn * 32 + nt * 8 + cq;
                    float v0 = ftanh(acc[i][nt][2 * h + 0] + __ldg(bd2 + col));
                    float v1 = ftanh(acc[i][nt][2 * h + 1] + __ldg(bd2 + col + 1));
                    *reinterpret_cast<float2*>(crow + col) = make_float2(v0, v1);
                }
            }
    }
}

// ---------------------------------------------------------------------------
extern "C" void kernel_launch(void* const* d_in, const int* in_sizes, int n_in,
                              void* d_out, int out_size)
{
    (void)in_sizes; (void)n_in; (void)out_size;
    const float* in_seq = (const float*)d_in[0];
    const float* L      = (const float*)d_in[1];
    const float* Rm     = (const float*)d_in[2];
    const float* Wz     = (const float*)d_in[3];
    const float* Az_w   = (const float*)d_in[4];
    const float* Az_b   = (const float*)d_in[5];
    const float* ex1_w  = (const float*)d_in[6];
    const float* ex1_b  = (const float*)d_in[7];
    const float* ex2_w  = (const float*)d_in[8];
    const float* ex2_b  = (const float*)d_in[9];
    const float* ex3_w  = (const float*)d_in[10];
    const float* ex3_b  = (const float*)d_in[11];
    const float* ez1_w  = (const float*)d_in[12];
    const float* ez1_b  = (const float*)d_in[13];
    const float* ez2_w  = (const float*)d_in[14];
    const float* ez2_b  = (const float*)d_in[15];
    const float* ez3_w  = (const float*)d_in[16];
    const float* ez3_b  = (const float*)d_in[17];
    const float* de1_w  = (const float*)d_in[18];
    const float* de1_b  = (const float*)d_in[19];
    const float* de2_w  = (const float*)d_in[20];
    const float* de2_b  = (const float*)d_in[21];

    float* out    = (float*)d_out;
    float* x_pred = out;
    float* x_rec  = out + (size_t)BB*TT*PP;
    float* z_pred = out + 2*(size_t)BB*TT*PP;
    float* z_seq  = z_pred + (size_t)BB*TT*MM;

    const int SMF = (33792 + 69632) * 2;   // 206848 B
    cudaFuncSetAttribute(fused_xz,  cudaFuncAttributeMaxDynamicSharedMemorySize, SMF);
    cudaFuncSetAttribute(fused_dec, cudaFuncAttributeMaxDynamicSharedMemorySize, SMF);

    // 1. weight conversions + step-weight pack (small)
    {
        const int TOT = W_TOTAL/4 + P_TOT;
        conv_kernel<<<(TOT + 255) / 256, 256>>>(ex1_w, ex2_w, ex3_w,
                                                ez1_w, ez2_w, ez3_w, de1_w, de2_w,
                                                Wz, Az_w, Az_b, L, Rm);
    }

    // 2. fully fused encoder/decoder chain (x + z) — seeds scan state too
    fused_xz<<<NROWS/128, 512, SMF>>>(in_seq,
                                      ex1_b, ex2_b, ex3_b,
                                      ez1_b, ez2_b, ez3_b,
                                      de1_b, de2_b, x_rec, z_seq);

    // 3. all 5 recurrence sub-steps in one launch (4 rows/warp)
    mega_step<<<NR/32, 256>>>(z_pred);

    // 4. one decoder launch over all 5 step snapshots
    fused_dec<<<5 * (NRP/128), 512, SMF>>>(de1_b, de2_b, x_pred);
}

// round 16
// speedup vs baseline: 1.1198x; 1.1198x over previous
#include <cuda_runtime.h>
#include <cuda_fp16.h>
#include <math.h>
#include <stdint.h>

// Problem constants
#define BB 32
#define TT 2048
#define PP 128
#define KK 256
#define MM 64
#define CCH 410            // independent 5-step chunks
#define NR (BB*CCH)        // 13120 state rows
#define NRP 13184          // NR padded to 128 multiple (also 64-mult: 206*64)
#define NROWS (BB*TT)      // 65536 encoder rows

// fp16 weight pack offsets (in halfs)
#define W_EX1 0
#define W_EX2 32768
#define W_EX3 98304
#define W_EZ1 163840
#define W_EZ2 172032
#define W_EZ3 176128
#define W_DE1 180224
#define W_DE2 245760
#define W_TOTAL 278528

// fp32 step-weight pack offsets (floats)
#define P_WZT 0        // 64x64 transposed
#define P_AZT 4096     // 8x68 row-major (pitch 68)
#define P_L   4640     // 256x12 (pitch 12)
#define P_RT  7712     // 8x256 transposed
#define P_AZB 9760     // 8
#define P_TOT 9768

// Scratch (device globals; zero-initialized)
__device__ __half g_w16[W_TOTAL];
__device__ float  g_step[P_TOT];
__device__ float  g_X[NRP*KK];                  // fp32 scan-state init; pad rows 0
__device__ float  g_Z[NR*MM];
__device__ __half g_X16s[(size_t)5*NRP*KK];     // per-step x snapshots; pad rows 0

// ---------------------------------------------------------------------------
// helpers
// ---------------------------------------------------------------------------
__device__ __forceinline__ void cpa16(uint32_t dst, const void* src) {
    asm volatile("cp.async.cg.shared.global [%0], [%1], 16;\n"
                 :: "r"(dst), "l"(src));
}
__device__ __forceinline__ void commitg() {
    asm volatile("cp.async.commit_group;\n" ::: "memory");
}
template<int N> __device__ __forceinline__ void waitg() {
    asm volatile("cp.async.wait_group %0;\n" :: "n"(N) : "memory");
}
__device__ __forceinline__ void ldsm4(uint32_t* r, uint32_t addr) {
    asm volatile("ldmatrix.sync.aligned.m8n8.x4.shared.b16 {%0,%1,%2,%3}, [%4];\n"
        : "=r"(r[0]), "=r"(r[1]), "=r"(r[2]), "=r"(r[3]) : "r"(addr));
}
__device__ __forceinline__ void mma16816(float* c, const uint32_t* a,
                                         uint32_t b0, uint32_t b1) {
    asm volatile(
      "mma.sync.aligned.m16n8k16.row.col.f32.f16.f16.f32 "
      "{%0,%1,%2,%3}, {%4,%5,%6,%7}, {%8,%9}, {%0,%1,%2,%3};\n"
      : "+f"(c[0]), "+f"(c[1]), "+f"(c[2]), "+f"(c[3])
      : "r"(a[0]), "r"(a[1]), "r"(a[2]), "r"(a[3]), "r"(b0), "r"(b1));
}
// accurate fast tanh (abs err ~1e-7): all output-facing tanh
__device__ __forceinline__ float ftanh(float x) {
    float e = __expf(2.0f * x);
    return 1.0f - __fdividef(2.0f, e + 1.0f);
}
// hardware tanh approx: recurrence-internal only (error attenuated by /100)
__device__ __forceinline__ float htanh(float x) {
    float y; asm("tanh.approx.f32 %0, %1;" : "=f"(y) : "f"(x)); return y;
}

// ---------------------------------------------------------------------------
// One-time conversion: weights -> fp16; step weights -> packed fp32
// ---------------------------------------------------------------------------
__global__ void conv_kernel(const float* __restrict__ ex1, const float* __restrict__ ex2,
                            const float* __restrict__ ex3, const float* __restrict__ ez1,
                            const float* __restrict__ ez2, const float* __restrict__ ez3,
                            const float* __restrict__ de1, const float* __restrict__ de2,
                            const float* __restrict__ Wz,  const float* __restrict__ Azw,
                            const float* __restrict__ Azb, const float* __restrict__ Lw,
                            const float* __restrict__ Rm)
{
    int i4 = blockIdx.x * blockDim.x + threadIdx.x;
    int j = i4 * 4;
    if (j < W_TOTAL) {
        const float* src; int off;
        if      (j < W_EX2) { src = ex1; off = W_EX1; }
        else if (j < W_EX3) { src = ex2; off = W_EX2; }
        else if (j < W_EZ1) { src = ex3; off = W_EX3; }
        else if (j < W_EZ2) { src = ez1; off = W_EZ1; }
        else if (j < W_EZ3) { src = ez2; off = W_EZ2; }
        else if (j < W_DE1) { src = ez3; off = W_EZ3; }
        else if (j < W_DE2) { src = de1; off = W_DE1; }
        else                { src = de2; off = W_DE2; }
        float4 v = reinterpret_cast<const float4*>(src)[(j - off) >> 2];
        __half2 a = __floats2half2_rn(v.x, v.y), b = __floats2half2_rn(v.z, v.w);
        uint2 u = { *reinterpret_cast<unsigned*>(&a), *reinterpret_cast<unsigned*>(&b) };
        *reinterpret_cast<uint2*>(&g_w16[j]) = u;
        return;
    }
    int sidx = i4 - W_TOTAL/4;
    if (sidx >= P_TOT) return;
    float v;
    if (sidx < P_AZT) {
        v = Wz[(sidx & 63)*64 + (sidx >> 6)];
    } else if (sidx < P_L) {
        int q = sidx - P_AZT;
        int row = q / 68, col = q % 68;
        v = (col < 64) ? Azw[row*64 + col] : 0.f;
    } else if (sidx < P_RT) {
        int q = sidx - P_L;
        int row = q / 12, col = q % 12;
        v = (col < 8) ? Lw[row*8 + col] : 0.f;
    } else if (sidx < P_AZB) {
        int q = sidx - P_RT;
        v = Rm[(q & 255)*8 + (q >> 8)];
    } else {
        v = Azb[sidx - P_AZB];
    }
    g_step[sidx] = v;
}

// ---------------------------------------------------------------------------
// Issue one BK=64 weight stage (Nd rows x 64 halfs) of layer gW (row stride
// Kd) into ring slot `slot` (slot stride 256 x 72 halfs). 256 threads.
// ---------------------------------------------------------------------------
template<int Nd, int Kd>
__device__ __forceinline__ void issueB(const __half* __restrict__ gW, int t,
                                       int slot, uint32_t bBase)
{
    constexpr int CH = Nd * 8;
    const int tid = threadIdx.x;
    #pragma unroll
    for (int c = tid; c < CH; c += 256) {
        int row = c >> 3, off = (c & 7) << 3;
        cpa16(bBase + (uint32_t)(((slot * 256 + row) * 72 + off) * 2),
              gW + (size_t)row * Kd + t * 64 + off);
    }
}

// ---------------------------------------------------------------------------
// gemm64: acc(64 x Nd) += sA(64 x Kd, pitch Kd+8) @ gW(Nd x Kd)^T
// 256 threads, 8 warps 2m x 4n, warp tile 32 x (Nd/4). BK=64, 2-slot ring,
// depth-1 stream: stage s top = waitg<0>+sync, issue stage s+1 (or chain()),
// commit, compute slot (SBASE+s)&1. Entry: stage0 = newest commit, slot SBASE.
// ---------------------------------------------------------------------------
template<int Nd, int Kd, int NT, int SBASE, typename F>
__device__ __forceinline__ void gemm64(const __half* __restrict__ gW,
                                       const __half* sA, __half* sB,
                                       float (&acc)[2][NT][4], F&& chain)
{
    constexpr int BK = 64, BP = 72, AP = Kd + 8;
    constexpr int S = Kd / BK;
    constexpr int WN = Nd / 4;
    static_assert(NT == WN / 8, "NT mismatch");

    const int tid = threadIdx.x, lane = tid & 31, wid = tid >> 5;
    const int wm = wid & 1, wn = wid >> 1;
    const uint32_t aBase = (uint32_t)__cvta_generic_to_shared(sA);
    const uint32_t bBase = (uint32_t)__cvta_generic_to_shared(sB);
    const int arow = wm * 32 + (lane & 15);
    const int akof = (lane >> 4) << 3;
    const int brow = wn * WN + (lane & 7) + ((lane >> 4) << 3);
    const int bkof = ((lane >> 3) & 1) << 3;

    #pragma unroll
    for (int i = 0; i < 2; i++)
        #pragma unroll
        for (int j = 0; j < NT; j++)
            #pragma unroll
            for (int q = 0; q < 4; q++) acc[i][j][q] = 0.f;

    #pragma unroll
    for (int s = 0; s < S; s++) {
        waitg<0>();
        __syncthreads();
        if (s + 1 < S) issueB<Nd, Kd>(gW, s + 1, (SBASE + s + 1) & 1, bBase);
        else           chain(0);
        commitg();
        const int slot = (SBASE + s) & 1;
        #pragma unroll
        for (int kk = 0; kk < BK; kk += 16) {
            uint32_t af[2][4];
            uint32_t aa = aBase + (uint32_t)((arow * AP + s * BK + kk + akof) * 2);
            ldsm4(af[0], aa);
            ldsm4(af[1], aa + 16 * AP * 2);
            #pragma unroll
            for (int j2 = 0; j2 < NT / 2; j2++) {
                uint32_t bf[4];
                ldsm4(bf, bBase + (uint32_t)(((slot * 256 + brow + j2 * 16) * BP + kk + bkof) * 2));
                mma16816(acc[0][2 * j2],     af[0], bf[0], bf[1]);
                mma16816(acc[0][2 * j2 + 1], af[0], bf[2], bf[3]);
                mma16816(acc[1][2 * j2],     af[1], bf[0], bf[1]);
                mma16816(acc[1][2 * j2 + 1], af[1], bf[2], bf[3]);
            }
        }
    }
}

// ---------------------------------------------------------------------------
// Epilogue: ftanh(acc + bias) -> pitched smem (pitch Nd + 8); 2m x 4n warps
// ---------------------------------------------------------------------------
template<int Nd, int NT>
__device__ __forceinline__ void epi_to_smem(float (&acc)[2][NT][4],
        const float* __restrict__ bias, __half* sOut)
{
    constexpr int WN = Nd / 4, OP = Nd + 8;
    const int tid = threadIdx.x, lane = tid & 31, wid = tid >> 5;
    const int wm = wid & 1, wn = wid >> 1;
    const int g = lane >> 2, cq = (lane & 3) << 1;
    #pragma unroll
    for (int i = 0; i < 2; i++)
        #pragma unroll
        for (int h = 0; h < 2; h++) {
            const int row = wm * 32 + i * 16 + h * 8 + g;
            #pragma unroll
            for (int nt = 0; nt < NT; nt++) {
                const int col = wn * WN + nt * 8 + cq;
                float v0 = ftanh(acc[i][nt][2 * h + 0] + __ldg(bias + col));
                float v1 = ftanh(acc[i][nt][2 * h + 1] + __ldg(bias + col + 1));
                *reinterpret_cast<__half2*>(sOut + row * OP + col) =
                    __floats2half2_rn(v0, v1);
            }
        }
}

// ---------------------------------------------------------------------------
// fused_xz (256 thr, BM=64, 2 CTAs/SM): per 64-row tile:
// ez1 -> ez2 -> ez3 (z_seq + Z init) -> ex1 -> ex2 -> ex3 (X init)
// -> de1 -> de2 -> x_rec.
// smem halfs: sA 16896 (in16 @136 first 8704; zQ 64x72 at +8704) | sB 36864
// = 107520 B total.
// ---------------------------------------------------------------------------
__global__ void __launch_bounds__(256, 2)
fused_xz(const float* __restrict__ in_seq,
         const float* __restrict__ bx1, const float* __restrict__ bx2,
         const float* __restrict__ bx3, const float* __restrict__ bz1,
         const float* __restrict__ bz2, const float* __restrict__ bz3,
         const float* __restrict__ bd1, const float* __restrict__ bd2,
         float* __restrict__ x_rec, float* __restrict__ z_seq)
{
    extern __shared__ __half sm[];
    __half* sA = sm;                   // 16896 halfs (in16 @136, act @264)
    __half* zQ = sm + 8704;            // 4608 halfs (64x72), in16 slack
    __half* sB = sm + 16896;           // 36864 halfs (2 x 256 x 72)
    const uint32_t bB = (uint32_t)__cvta_generic_to_shared(sB);
    const int row0 = blockIdx.x * 64;
    const int tid = threadIdx.x, lane = tid & 31, wid = tid >> 5;
    const int wm = wid & 1, wn = wid >> 1;
    const int g = lane >> 2, cq = (lane & 3) << 1;

    // prefill: ez1 stage0 -> slot0
    issueB<64, 128>(g_w16 + W_EZ1, 0, 0, bB); commitg();

    // in_seq fp32 -> fp16 tile (pitch 136) in sA (covers stage0 latency)
    #pragma unroll
    for (int c = tid; c < 64 * 32; c += 256) {
        int row = c >> 5, off = (c & 31) << 2;
        float4 v = *reinterpret_cast<const float4*>(
            in_seq + (size_t)(row0 + row) * PP + off);
        __half2 a = __floats2half2_rn(v.x, v.y), b = __floats2half2_rn(v.z, v.w);
        uint2 u = { *reinterpret_cast<unsigned*>(&a), *reinterpret_cast<unsigned*>(&b) };
        *reinterpret_cast<uint2*>(&sA[row * 136 + off]) = u;
    }

    // ez1 (in16 -> zQ); S=2 (slots 0,1); chain ez2 s0 -> slot0
    {   float acc[2][2][4];
        gemm64<64, 128, 2, 0>(g_w16 + W_EZ1, sA, sB, acc, [&](int){
            issueB<64, 64>(g_w16 + W_EZ2, 0, 0, bB);
        });
        epi_to_smem<64, 2>(acc, bz1, zQ);
    }
    // ez2 (zQ -> in-place zQ); S=1 (slot0); chain ez3 s0 -> slot1
    {   float acc[2][2][4];
        gemm64<64, 64, 2, 0>(g_w16 + W_EZ2, zQ, sB, acc, [&](int){
            issueB<64, 64>(g_w16 + W_EZ3, 0, 1, bB);
        });
        __syncthreads();
        epi_to_smem<64, 2>(acc, bz2, zQ);
    }
    // ez3 (slot1) -> z_seq fp32 + Z init; chain ex1 s0 -> slot0
    {   float acc[2][2][4];
        gemm64<64, 64, 2, 1>(g_w16 + W_EZ3, zQ, sB, acc, [&](int){
            issueB<256, 128>(g_w16 + W_EX1, 0, 0, bB);
        });
        #pragma unroll
        for (int i = 0; i < 2; i++)
            #pragma unroll
            for (int h = 0; h < 2; h++) {
                const int row = wm * 32 + i * 16 + h * 8 + g;
                const int r = row0 + row;
                const int t = r & (TT - 1);
                const int rs = (t % 5 == 0) ? ((r >> 11) * CCH + t / 5) : -1;
                #pragma unroll
                for (int nt = 0; nt < 2; nt++) {
                    const int col = wn * 16 + nt * 8 + cq;
                    float v0 = ftanh(acc[i][nt][2 * h + 0] + __ldg(bz3 + col));
                    float v1 = ftanh(acc[i][nt][2 * h + 1] + __ldg(bz3 + col + 1));
                    *reinterpret_cast<float2*>(z_seq + (size_t)r * MM + col) =
                        make_float2(v0, v1);
                    if (rs >= 0)
                        *reinterpret_cast<float2*>(&g_Z[(size_t)rs * MM + col]) =
                            make_float2(v0, v1);
                }
            }
    }
    // ex1 (in16 -> in-place sA); S=2 (slots 0,1); chain ex2 s0 -> slot0
    {   float acc[2][8][4];
        gemm64<256, 128, 8, 0>(g_w16 + W_EX1, sA, sB, acc, [&](int){
            issueB<256, 256>(g_w16 + W_EX2, 0, 0, bB);
        });
        __syncthreads();
        epi_to_smem<256, 8>(acc, bx1, sA);
    }
    // ex2 (sA -> sA); S=4; chain ex3 s0 -> slot0
    {   float acc[2][8][4];
        gemm64<256, 256, 8, 0>(g_w16 + W_EX2, sA, sB, acc, [&](int){
            issueB<256, 256>(g_w16 + W_EX3, 0, 0, bB);
        });
        __syncthreads();
        epi_to_smem<256, 8>(acc, bx2, sA);
    }
    // ex3 (sA -> sA) + fp32 X init; chain de1 s0 -> slot0
    {   float acc[2][8][4];
        gemm64<256, 256, 8, 0>(g_w16 + W_EX3, sA, sB, acc, [&](int){
            issueB<256, 256>(g_w16 + W_DE1, 0, 0, bB);
        });
        __syncthreads();
        #pragma unroll
        for (int i = 0; i < 2; i++)
            #pragma unroll
            for (int h = 0; h < 2; h++) {
                const int row = wm * 32 + i * 16 + h * 8 + g;
                const int r = row0 + row;
                const int t = r & (TT - 1);
                const int rs = (t % 5 == 0) ? ((r >> 11) * CCH + t / 5) : -1;
                #pragma unroll
                for (int nt = 0; nt < 8; nt++) {
                    const int col = wn * 64 + nt * 8 + cq;
                    float v0 = ftanh(acc[i][nt][2 * h + 0] + __ldg(bx3 + col));
                    float v1 = ftanh(acc[i][nt][2 * h + 1] + __ldg(bx3 + col + 1));
                    *reinterpret_cast<__half2*>(sA + row * 264 + col) =
                        __floats2half2_rn(v0, v1);
                    if (rs >= 0)
                        *reinterpret_cast<float2*>(&g_X[(size_t)rs * KK + col]) =
                            make_float2(v0, v1);
                }
            }
    }
    // de1 (sA -> sA); chain de2 s0 -> slot0
    {   float acc[2][8][4];
        gemm64<256, 256, 8, 0>(g_w16 + W_DE1, sA, sB, acc, [&](int){
            issueB<128, 256>(g_w16 + W_DE2, 0, 0, bB);
        });
        __syncthreads();
        epi_to_smem<256, 8>(acc, bd1, sA);
    }
    // de2 -> x_rec (fp32 dense)
    {   float acc[2][4][4];
        gemm64<128, 256, 4, 0>(g_w16 + W_DE2, sA, sB, acc, [](int){});
        #pragma unroll
        for (int i = 0; i < 2; i++)
            #pragma unroll
            for (int h = 0; h < 2; h++) {
                const int row = wm * 32 + i * 16 + h * 8 + g;
                const int r = row0 + row;
                #pragma unroll
                for (int nt = 0; nt < 4; nt++) {
                    const int col = wn * 32 + nt * 8 + cq;
                    float v0 = ftanh(acc[i][nt][2 * h + 0] + __ldg(bd2 + col));
                    float v1 = ftanh(acc[i][nt][2 * h + 1] + __ldg(bd2 + col + 1));
                    *reinterpret_cast<float2*>(x_rec + (size_t)r * PP + col) =
                        make_float2(v0, v1);
                }
            }
    }
}

// ---------------------------------------------------------------------------
// mega_step (R11 version): all 5 recurrence sub-steps; 4 rows per warp,
// state in registers; conflict-free gate reads (Az pitch 68).
// ---------------------------------------------------------------------------
__global__ void __launch_bounds__(256, 2)
mega_step(float* __restrict__ zpred)
{
    __shared__ __align__(16) float sP[P_TOT];
    __shared__ __align__(16) float stz[8][4][68];

    const int tid = threadIdx.x;
    for (int i = tid; i < P_TOT; i += 256) sP[i] = g_step[i];
    __syncthreads();
    const float*  sWzT = sP + P_WZT;
    const float*  sAzQ = sP + P_AZT;
    const float4* sL4  = (const float4*)(sP + P_L);
    const float*  sRT  = sP + P_RT;
    const float*  sAzb = sP + P_AZB;

    const int w = tid >> 5, lane = tid & 31;
    const int r0 = (blockIdx.x * 8 + w) * 4;
    const int gr = lane >> 3, gq = lane & 7;

    int tbase[4]; size_t zoff[4];
    float zv0[4], zv1[4], xv[4][8];
    #pragma unroll
    for (int r = 0; r < 4; r++) {
        const int rr = r0 + r;
        const int b = rr / CCH, c = rr % CCH;
        tbase[r] = 5 * c;
        zoff[r]  = ((size_t)b * TT) * MM;
        zv0[r] = g_Z[(size_t)rr * MM + lane];
        zv1[r] = g_Z[(size_t)rr * MM + 32 + lane];
        #pragma unroll
        for (int k = 0; k < 8; k++)
            xv[r][k] = g_X[(size_t)rr * KK + lane + 32 * k];
    }

    #pragma unroll 1
    for (int s = 0; s < 5; s++) {
        #pragma unroll
        for (int r = 0; r < 4; r++) {
            stz[w][r][lane]      = htanh(zv0[r]);
            stz[w][r][lane + 32] = htanh(zv1[r]);
        }
        __syncwarp();
        float a0[4] = {0.f,0.f,0.f,0.f}, a1[4] = {0.f,0.f,0.f,0.f};
        #pragma unroll
        for (int i4 = 0; i4 < 16; i4++) {
            float4 tz[4];
            #pragma unroll
            for (int r = 0; r < 4; r++)
                tz[r] = *(const float4*)&stz[w][r][i4 * 4];
            const float* wr = sWzT + (i4 * 4) * 64 + lane;
            #pragma unroll
            for (int ii = 0; ii < 4; ii++) {
                const float w0 = wr[ii * 64], w1 = wr[ii * 64 + 32];
                const float c0 = (ii == 0) ? tz[0].x : (ii == 1) ? tz[0].y
                               : (ii == 2) ? tz[0].z : tz[0].w;
                const float c1 = (ii == 0) ? tz[1].x : (ii == 1) ? tz[1].y
                               : (ii == 2) ? tz[1].z : tz[1].w;
                const float c2 = (ii == 0) ? tz[2].x : (ii == 1) ? tz[2].y
                               : (ii == 2) ? tz[2].z : tz[2].w;
                const float c3 = (ii == 0) ? tz[3].x : (ii == 1) ? tz[3].y
                               : (ii == 2) ? tz[3].z : tz[3].w;
                a0[0] = fmaf(c0, w0, a0[0]);  a1[0] = fmaf(c0, w1, a1[0]);
                a0[1] = fmaf(c1, w0, a0[1]);  a1[1] = fmaf(c1, w1, a1[1]);
                a0[2] = fmaf(c2, w0, a0[2]);  a1[2] = fmaf(c2, w1, a1[2]);
                a0[3] = fmaf(c3, w0, a0[3]);  a1[3] = fmaf(c3, w1, a1[3]);
            }
        }
        #pragma unroll
        for (int r = 0; r < 4; r++) {
            zv0[r] = zv0[r] + (a0[r] - zv0[r]) * 0.01f;
            zv1[r] = zv1[r] + (a1[r] - zv1[r]) * 0.01f;
        }
        __syncwarp();
        #pragma unroll
        for (int r = 0; r < 4; r++) {
            stz[w][r][lane]      = zv0[r];
            stz[w][r][lane + 32] = zv1[r];
        }
        __syncwarp();
        float ga = 0.f;
        {
            const float4* az4 = (const float4*)(sAzQ + gq * 68);
            const float4* zz4 = (const float4*)&stz[w][gr][0];
            #pragma unroll
            for (int i4 = 0; i4 < 16; i4++) {
                float4 a = az4[i4], z = zz4[i4];
                ga = fmaf(z.x, a.x, ga);
                ga = fmaf(z.y, a.y, ga);
                ga = fmaf(z.z, a.z, ga);
                ga = fmaf(z.w, a.w, ga);
            }
        }
        const float sg = 1.f / (1.f + __expf(-(ga + sAzb[gq])));
        float gu[4][8];
        #pragma unroll
        for (int r = 0; r < 4; r++)
            #pragma unroll
            for (int q = 0; q < 8; q++) gu[r][q] = 0.f;
        #pragma unroll
        for (int k = 0; k < 8; k++) {
            const int j = lane + 32 * k;
            const float4 l0 = sL4[j * 3], l1 = sL4[j * 3 + 1];
            #pragma unroll
            for (int r = 0; r < 4; r++) {
                const float tx = htanh(xv[r][k]);
                gu[r][0] = fmaf(tx, l0.x, gu[r][0]);
                gu[r][1] = fmaf(tx, l0.y, gu[r][1]);
                gu[r][2] = fmaf(tx, l0.z, gu[r][2]);
                gu[r][3] = fmaf(tx, l0.w, gu[r][3]);
                gu[r][4] = fmaf(tx, l1.x, gu[r][4]);
                gu[r][5] = fmaf(tx, l1.y, gu[r][5]);
                gu[r][6] = fmaf(tx, l1.z, gu[r][6]);
                gu[r][7] = fmaf(tx, l1.w, gu[r][7]);
            }
        }
        #pragma unroll
        for (int off = 16; off > 0; off >>= 1)
            #pragma unroll
            for (int r = 0; r < 4; r++)
                #pragma unroll
                for (int q = 0; q < 8; q++)
                    gu[r][q] += __shfl_xor_sync(0xffffffffu, gu[r][q], off);
        #pragma unroll
        for (int r = 0; r < 4; r++)
            #pragma unroll
            for (int q = 0; q < 8; q++)
                gu[r][q] *= __shfl_sync(0xffffffffu, sg, r * 8 + q);
        #pragma unroll
        for (int k = 0; k < 8; k++) {
            const int j = lane + 32 * k;
            float acc[4] = {0.f,0.f,0.f,0.f};
            #pragma unroll
            for (int q = 0; q < 8; q++) {
                const float wv = sRT[q * 256 + j];
                acc[0] = fmaf(gu[0][q], wv, acc[0]);
                acc[1] = fmaf(gu[1][q], wv, acc[1]);
                acc[2] = fmaf(gu[2][q], wv, acc[2]);
                acc[3] = fmaf(gu[3][q], wv, acc[3]);
            }
            #pragma unroll
            for (int r = 0; r < 4; r++)
                xv[r][k] = xv[r][k] + (acc[r] - xv[r][k]) * 0.01f;
        }
        #pragma unroll
        for (int r = 0; r < 4; r++) {
            const int t = tbase[r] + s;
            if (t < TT) {
                float* zp = zpred + zoff[r] + (size_t)t * MM;
                zp[lane]      = zv0[r];
                zp[lane + 32] = zv1[r];
            }
            __half* xd = g_X16s + ((size_t)s * NRP + (r0 + r)) * KK;
            #pragma unroll
            for (int k = 0; k < 8; k++)
                xd[lane + 32 * k] = __float2half(xv[r][k]);
        }
    }
}

// ---------------------------------------------------------------------------
// fused_dec (256 thr, BM=64, 2 CTAs/SM): X16s -> de1 -> de2 -> x_pred scatter
// smem halfs: sA 16896 | sB 36864 = 107520 B
// ---------------------------------------------------------------------------
__global__ void __launch_bounds__(256, 2)
fused_dec(const float* __restrict__ bd1, const float* __restrict__ bd2,
          float* __restrict__ x_pred)
{
    extern __shared__ __half sm[];
    __half* sA = sm;
    __half* sB = sm + 16896;
    const uint32_t bB = (uint32_t)__cvta_generic_to_shared(sB);
    const int s    = blockIdx.x / (NRP / 64);
    const int row0 = (blockIdx.x % (NRP / 64)) * 64;
    const int tid = threadIdx.x, lane = tid & 31, wid = tid >> 5;
    const int wm = wid & 1, wn = wid >> 1;
    const int g = lane >> 2, cq = (lane & 3) << 1;

    // A tile + de1 stage0 (slot0); gemm entry waitg<0> drains both
    {
        const __half* gA = g_X16s + ((size_t)s * NRP + row0) * KK;
        uint32_t d = (uint32_t)__cvta_generic_to_shared(sA);
        #pragma unroll
        for (int c = tid; c < 64 * 32; c += 256) {
            int row = c >> 5, off = (c & 31) << 3;
            cpa16(d + (uint32_t)((row * 264 + off) * 2), gA + (size_t)row * KK + off);
        }
        commitg();
        issueB<256, 256>(g_w16 + W_DE1, 0, 0, bB); commitg();
    }

    // de1; chain de2 s0 -> slot0
    {   float acc[2][8][4];
        gemm64<256, 256, 8, 0>(g_w16 + W_DE1, sA, sB, acc, [&](int){
            issueB<128, 256>(g_w16 + W_DE2, 0, 0, bB);
        });
        __syncthreads();
        epi_to_smem<256, 8>(acc, bd1, sA);
    }
    // de2 -> scatter x_pred
    {   float acc[2][4][4];
        gemm64<128, 256, 4, 0>(g_w16 + W_DE2, sA, sB, acc, [](int){});
        #pragma unroll
        for (int i = 0; i < 2; i++)
            #pragma unroll
            for (int h = 0; h < 2; h++) {
                const int row = wm * 32 + i * 16 + h * 8 + g;
                const int r = row0 + row;
                if (r >= NR) continue;
                const int b = r / CCH, c = r % CCH;
                const int t = 5 * c + s;
                if (t >= TT) continue;
                float* crow = x_pred + ((size_t)b * TT + t) * PP;
                #pragma unroll
                for (int nt = 0; nt < 4; nt++) {
                    const int col = wn * 32 + nt * 8 + cq;
                    float v0 = ftanh(acc[i][nt][2 * h + 0] + __ldg(bd2 + col));
                    float v1 = ftanh(acc[i][nt][2 * h + 1] + __ldg(bd2 + col + 1));
                    *reinterpret_cast<float2*>(crow + col) = make_float2(v0, v1);
                }
            }
    }
}

// ---------------------------------------------------------------------------
extern "C" void kernel_launch(void* const* d_in, const int* in_sizes, int n_in,
                              void* d_out, int out_size)
{
    (void)in_sizes; (void)n_in; (void)out_size;
    const float* in_seq = (const float*)d_in[0];
    const float* L      = (const float*)d_in[1];
    const float* Rm     = (const float*)d_in[2];
    const float* Wz     = (const float*)d_in[3];
    const float* Az_w   = (const float*)d_in[4];
    const float* Az_b   = (const float*)d_in[5];
    const float* ex1_w  = (const float*)d_in[6];
    const float* ex1_b  = (const float*)d_in[7];
    const float* ex2_w  = (const float*)d_in[8];
    const float* ex2_b  = (const float*)d_in[9];
    const float* ex3_w  = (const float*)d_in[10];
    const float* ex3_b  = (const float*)d_in[11];
    const float* ez1_w  = (const float*)d_in[12];
    const float* ez1_b  = (const float*)d_in[13];
    const float* ez2_w  = (const float*)d_in[14];
    const float* ez2_b  = (const float*)d_in[15];
    const float* ez3_w  = (const float*)d_in[16];
    const float* ez3_b  = (const float*)d_in[17];
    const float* de1_w  = (const float*)d_in[18];
    const float* de1_b  = (const float*)d_in[19];
    const float* de2_w  = (const float*)d_in[20];
    const float* de2_b  = (const float*)d_in[21];

    float* out    = (float*)d_out;
    float* x_pred = out;
    float* x_rec  = out + (size_t)BB*TT*PP;
    float* z_pred = out + 2*(size_t)BB*TT*PP;
    float* z_seq  = z_pred + (size_t)BB*TT*MM;

    const int SMF = (16896 + 36864) * 2;   // 107520 B -> 2 CTAs/SM
    cudaFuncSetAttribute(fused_xz,  cudaFuncAttributeMaxDynamicSharedMemorySize, SMF);
    cudaFuncSetAttribute(fused_dec, cudaFuncAttributeMaxDynamicSharedMemorySize, SMF);

    // 1. weight conversions + step-weight pack (small)
    {
        const int TOT = W_TOTAL/4 + P_TOT;
        conv_kernel<<<(TOT + 255) / 256, 256>>>(ex1_w, ex2_w, ex3_w,
                                                ez1_w, ez2_w, ez3_w, de1_w, de2_w,
                                                Wz, Az_w, Az_b, L, Rm);
    }

    // 2. fully fused encoder/decoder chain (x + z) — seeds scan state too
    fused_xz<<<NROWS/64, 256, SMF>>>(in_seq,
                                     ex1_b, ex2_b, ex3_b,
                                     ez1_b, ez2_b, ez3_b,
                                     de1_b, de2_b, x_rec, z_seq);

    // 3. all 5 recurrence sub-steps in one launch (4 rows/warp)
    mega_step<<<NR/32, 256>>>(z_pred);

    // 4. one decoder launch over all 5 step snapshots
    fused_dec<<<5 * (NRP/64), 256, SMF>>>(de1_b, de2_b, x_pred);
}

// round 17
// speedup vs baseline: 1.1445x; 1.0221x over previous
#include <cuda_runtime.h>
#include <cuda_fp16.h>
#include <math.h>
#include <stdint.h>

// Problem constants
#define BB 32
#define TT 2048
#define PP 128
#define KK 256
#define MM 64
#define CCH 410            // independent 5-step chunks
#define NR (BB*CCH)        // 13120 state rows
#define NRP 13184          // NR padded (64- and 128-multiple)
#define NROWS (BB*TT)      // 65536 encoder rows
#define NMEGA (NR/32)      // 410 recurrence blocks

// fp16 weight pack offsets (in halfs)
#define W_EX1 0
#define W_EX2 32768
#define W_EX3 98304
#define W_EZ1 163840
#define W_EZ2 172032
#define W_EZ3 176128
#define W_DE1 180224
#define W_DE2 245760
#define W_TOTAL 278528

// fp32 step-weight pack offsets (floats)
#define P_WZT 0        // 64x64 transposed
#define P_AZT 4096     // 8x68 row-major (pitch 68)
#define P_L   4640     // 256x12 (pitch 12)
#define P_RT  7712     // 8x256 transposed
#define P_AZB 9760     // 8
#define P_TOT 9768

// Scratch (device globals; zero-initialized)
__device__ __half g_w16[W_TOTAL];
__device__ float  g_step[P_TOT];
__device__ float  g_X[NRP*KK];                  // fp32 scan-state init; pad rows 0
__device__ float  g_Z[NR*MM];
__device__ __half g_xseq16[(size_t)NROWS*KK];   // encoder output (ex3)
__device__ __half g_X16s[(size_t)5*NRP*KK];     // per-step x snapshots; pad rows 0

// ---------------------------------------------------------------------------
// helpers
// ---------------------------------------------------------------------------
__device__ __forceinline__ void cpa16(uint32_t dst, const void* src) {
    asm volatile("cp.async.cg.shared.global [%0], [%1], 16;\n"
                 :: "r"(dst), "l"(src));
}
__device__ __forceinline__ void commitg() {
    asm volatile("cp.async.commit_group;\n" ::: "memory");
}
template<int N> __device__ __forceinline__ void waitg() {
    asm volatile("cp.async.wait_group %0;\n" :: "n"(N) : "memory");
}
__device__ __forceinline__ void ldsm4(uint32_t* r, uint32_t addr) {
    asm volatile("ldmatrix.sync.aligned.m8n8.x4.shared.b16 {%0,%1,%2,%3}, [%4];\n"
        : "=r"(r[0]), "=r"(r[1]), "=r"(r[2]), "=r"(r[3]) : "r"(addr));
}
__device__ __forceinline__ void mma16816(float* c, const uint32_t* a,
                                         uint32_t b0, uint32_t b1) {
    asm volatile(
      "mma.sync.aligned.m16n8k16.row.col.f32.f16.f16.f32 "
      "{%0,%1,%2,%3}, {%4,%5,%6,%7}, {%8,%9}, {%0,%1,%2,%3};\n"
      : "+f"(c[0]), "+f"(c[1]), "+f"(c[2]), "+f"(c[3])
      : "r"(a[0]), "r"(a[1]), "r"(a[2]), "r"(a[3]), "r"(b0), "r"(b1));
}
__device__ __forceinline__ float ftanh(float x) {
    float e = __expf(2.0f * x);
    return 1.0f - __fdividef(2.0f, e + 1.0f);
}
__device__ __forceinline__ float htanh(float x) {
    float y; asm("tanh.approx.f32 %0, %1;" : "=f"(y) : "f"(x)); return y;
}

// ---------------------------------------------------------------------------
// One-time conversion: weights -> fp16; step weights -> packed fp32
// ---------------------------------------------------------------------------
__global__ void conv_kernel(const float* __restrict__ ex1, const float* __restrict__ ex2,
                            const float* __restrict__ ex3, const float* __restrict__ ez1,
                            const float* __restrict__ ez2, const float* __restrict__ ez3,
                            const float* __restrict__ de1, const float* __restrict__ de2,
                            const float* __restrict__ Wz,  const float* __restrict__ Azw,
                            const float* __restrict__ Azb, const float* __restrict__ Lw,
                            const float* __restrict__ Rm)
{
    int i4 = blockIdx.x * blockDim.x + threadIdx.x;
    int j = i4 * 4;
    if (j < W_TOTAL) {
        const float* src; int off;
        if      (j < W_EX2) { src = ex1; off = W_EX1; }
        else if (j < W_EX3) { src = ex2; off = W_EX2; }
        else if (j < W_EZ1) { src = ex3; off = W_EX3; }
        else if (j < W_EZ2) { src = ez1; off = W_EZ1; }
        else if (j < W_EZ3) { src = ez2; off = W_EZ2; }
        else if (j < W_DE1) { src = ez3; off = W_EZ3; }
        else if (j < W_DE2) { src = de1; off = W_DE1; }
        else                { src = de2; off = W_DE2; }
        float4 v = reinterpret_cast<const float4*>(src)[(j - off) >> 2];
        __half2 a = __floats2half2_rn(v.x, v.y), b = __floats2half2_rn(v.z, v.w);
        uint2 u = { *reinterpret_cast<unsigned*>(&a), *reinterpret_cast<unsigned*>(&b) };
        *reinterpret_cast<uint2*>(&g_w16[j]) = u;
        return;
    }
    int sidx = i4 - W_TOTAL/4;
    if (sidx >= P_TOT) return;
    float v;
    if (sidx < P_AZT) {
        v = Wz[(sidx & 63)*64 + (sidx >> 6)];
    } else if (sidx < P_L) {
        int q = sidx - P_AZT;
        int row = q / 68, col = q % 68;
        v = (col < 64) ? Azw[row*64 + col] : 0.f;
    } else if (sidx < P_RT) {
        int q = sidx - P_L;
        int row = q / 12, col = q % 12;
        v = (col < 8) ? Lw[row*8 + col] : 0.f;
    } else if (sidx < P_AZB) {
        int q = sidx - P_RT;
        v = Rm[(q & 255)*8 + (q >> 8)];
    } else {
        v = Azb[sidx - P_AZB];
    }
    g_step[sidx] = v;
}

// ---------------------------------------------------------------------------
// Issue one BK=64 weight stage (Nd rows x 64 halfs) of layer gW (row stride
// Kd) into ring slot `slot` (slot stride 256 x 72 halfs). 256 threads.
// ---------------------------------------------------------------------------
template<int Nd, int Kd>
__device__ __forceinline__ void issueB(const __half* __restrict__ gW, int t,
                                       int slot, uint32_t bBase)
{
    constexpr int CH = Nd * 8;
    const int tid = threadIdx.x;
    #pragma unroll
    for (int c = tid; c < CH; c += 256) {
        int row = c >> 3, off = (c & 7) << 3;
        cpa16(bBase + (uint32_t)(((slot * 256 + row) * 72 + off) * 2),
              gW + (size_t)row * Kd + t * 64 + off);
    }
}

// ---------------------------------------------------------------------------
// gemm64: acc(64 x Nd) += sA(64 x Kd, pitch Kd+8) @ gW(Nd x Kd)^T
// 256 threads, 8 warps 2m x 4n, warp tile 32 x (Nd/4). BK=64, 2-slot ring.
// ---------------------------------------------------------------------------
template<int Nd, int Kd, int NT, int SBASE, typename F>
__device__ __forceinline__ void gemm64(const __half* __restrict__ gW,
                                       const __half* sA, __half* sB,
                                       float (&acc)[2][NT][4], F&& chain)
{
    constexpr int BK = 64, BP = 72, AP = Kd + 8;
    constexpr int S = Kd / BK;
    constexpr int WN = Nd / 4;
    static_assert(NT == WN / 8, "NT mismatch");

    const int tid = threadIdx.x, lane = tid & 31, wid = tid >> 5;
    const int wm = wid & 1, wn = wid >> 1;
    const uint32_t aBase = (uint32_t)__cvta_generic_to_shared(sA);
    const uint32_t bBase = (uint32_t)__cvta_generic_to_shared(sB);
    const int arow = wm * 32 + (lane & 15);
    const int akof = (lane >> 4) << 3;
    const int brow = wn * WN + (lane & 7) + ((lane >> 4) << 3);
    const int bkof = ((lane >> 3) & 1) << 3;

    #pragma unroll
    for (int i = 0; i < 2; i++)
        #pragma unroll
        for (int j = 0; j < NT; j++)
            #pragma unroll
            for (int q = 0; q < 4; q++) acc[i][j][q] = 0.f;

    #pragma unroll
    for (int s = 0; s < S; s++) {
        waitg<0>();
        __syncthreads();
        if (s + 1 < S) issueB<Nd, Kd>(gW, s + 1, (SBASE + s + 1) & 1, bBase);
        else           chain(0);
        commitg();
        const int slot = (SBASE + s) & 1;
        #pragma unroll
        for (int kk = 0; kk < BK; kk += 16) {
            uint32_t af[2][4];
            uint32_t aa = aBase + (uint32_t)((arow * AP + s * BK + kk + akof) * 2);
            ldsm4(af[0], aa);
            ldsm4(af[1], aa + 16 * AP * 2);
            #pragma unroll
            for (int j2 = 0; j2 < NT / 2; j2++) {
                uint32_t bf[4];
                ldsm4(bf, bBase + (uint32_t)(((slot * 256 + brow + j2 * 16) * BP + kk + bkof) * 2));
                mma16816(acc[0][2 * j2],     af[0], bf[0], bf[1]);
                mma16816(acc[0][2 * j2 + 1], af[0], bf[2], bf[3]);
                mma16816(acc[1][2 * j2],     af[1], bf[0], bf[1]);
                mma16816(acc[1][2 * j2 + 1], af[1], bf[2], bf[3]);
            }
        }
    }
}

// ---------------------------------------------------------------------------
// Epilogue: ftanh(acc + bias) -> pitched smem (pitch Nd + 8); 2m x 4n warps
// ---------------------------------------------------------------------------
template<int Nd, int NT>
__device__ __forceinline__ void epi_to_smem(float (&acc)[2][NT][4],
        const float* __restrict__ bias, __half* sOut)
{
    constexpr int WN = Nd / 4, OP = Nd + 8;
    const int tid = threadIdx.x, lane = tid & 31, wid = tid >> 5;
    const int wm = wid & 1, wn = wid >> 1;
    const int g = lane >> 2, cq = (lane & 3) << 1;
    #pragma unroll
    for (int i = 0; i < 2; i++)
        #pragma unroll
        for (int h = 0; h < 2; h++) {
            const int row = wm * 32 + i * 16 + h * 8 + g;
            #pragma unroll
            for (int nt = 0; nt < NT; nt++) {
                const int col = wn * WN + nt * 8 + cq;
                float v0 = ftanh(acc[i][nt][2 * h + 0] + __ldg(bias + col));
                float v1 = ftanh(acc[i][nt][2 * h + 1] + __ldg(bias + col + 1));
                *reinterpret_cast<__half2*>(sOut + row * OP + col) =
                    __floats2half2_rn(v0, v1);
            }
        }
}

// ---------------------------------------------------------------------------
// Decoder tile body: sA holds 64 x 256 fp16 activations (pitch 264).
// de1 -> de2, then MODE 0: dense x_rec rows; MODE 1: x_pred scatter (step s).
// ---------------------------------------------------------------------------
template<int MODE>
__device__ __forceinline__ void dec_body(__half* sA, __half* sB, uint32_t bB,
        const float* __restrict__ bd1, const float* __restrict__ bd2,
        float* __restrict__ outp, int row0, int s)
{
    const int tid = threadIdx.x, lane = tid & 31, wid = tid >> 5;
    const int wm = wid & 1, wn = wid >> 1;
    const int g = lane >> 2, cq = (lane & 3) << 1;

    {   float acc[2][8][4];
        gemm64<256, 256, 8, 0>(g_w16 + W_DE1, sA, sB, acc, [&](int){
            issueB<128, 256>(g_w16 + W_DE2, 0, 0, bB);
        });
        __syncthreads();
        epi_to_smem<256, 8>(acc, bd1, sA);
    }
    {   float acc[2][4][4];
        gemm64<128, 256, 4, 0>(g_w16 + W_DE2, sA, sB, acc, [](int){});
        #pragma unroll
        for (int i = 0; i < 2; i++)
            #pragma unroll
            for (int h = 0; h < 2; h++) {
                const int row = wm * 32 + i * 16 + h * 8 + g;
                const int r = row0 + row;
                float* crow;
                if (MODE == 0) {
                    crow = outp + (size_t)r * PP;
                } else {
                    if (r >= NR) continue;
                    const int b = r / CCH, c = r % CCH;
                    const int t = 5 * c + s;
                    if (t >= TT) continue;
                    crow = outp + ((size_t)b * TT + t) * PP;
                }
                #pragma unroll
                for (int nt = 0; nt < 4; nt++) {
                    const int col = wn * 32 + nt * 8 + cq;
                    float v0 = ftanh(acc[i][nt][2 * h + 0] + __ldg(bd2 + col));
                    float v1 = ftanh(acc[i][nt][2 * h + 1] + __ldg(bd2 + col + 1));
                    *reinterpret_cast<float2*>(crow + col) = make_float2(v0, v1);
                }
            }
    }
}

// Load a 64 x 256 fp16 gmem tile into sA (pitch 264) + de1 stage0 prefetch
__device__ __forceinline__ void dec_load(const __half* __restrict__ gA,
                                         __half* sA, uint32_t bB)
{
    const int tid = threadIdx.x;
    uint32_t d = (uint32_t)__cvta_generic_to_shared(sA);
    #pragma unroll
    for (int c = tid; c < 64 * 32; c += 256) {
        int row = c >> 5, off = (c & 31) << 3;
        cpa16(d + (uint32_t)((row * 264 + off) * 2), gA + (size_t)row * KK + off);
    }
    commitg();
    issueB<256, 256>(g_w16 + W_DE1, 0, 0, bB); commitg();
}

// ---------------------------------------------------------------------------
// fused_xz_enc (256 thr, BM=64, 2 CTAs/SM): encoders only.
// ez1 -> ez2 -> ez3 (z_seq + Z init) -> ex1 -> ex2 -> ex3 (xseq16 + X init)
// ---------------------------------------------------------------------------
__global__ void __launch_bounds__(256, 2)
fused_xz_enc(const float* __restrict__ in_seq,
             const float* __restrict__ bx1, const float* __restrict__ bx2,
             const float* __restrict__ bx3, const float* __restrict__ bz1,
             const float* __restrict__ bz2, const float* __restrict__ bz3,
             float* __restrict__ z_seq)
{
    extern __shared__ __half sm[];
    __half* sA = sm;                   // 16896 halfs (in16 @136, act @264)
    __half* zQ = sm + 8704;            // 4608 halfs (64x72), in16 slack
    __half* sB = sm + 16896;           // 36864 halfs
    const uint32_t bB = (uint32_t)__cvta_generic_to_shared(sB);
    const int row0 = blockIdx.x * 64;
    const int tid = threadIdx.x, lane = tid & 31, wid = tid >> 5;
    const int wm = wid & 1, wn = wid >> 1;
    const int g = lane >> 2, cq = (lane & 3) << 1;

    issueB<64, 128>(g_w16 + W_EZ1, 0, 0, bB); commitg();

    #pragma unroll
    for (int c = tid; c < 64 * 32; c += 256) {
        int row = c >> 5, off = (c & 31) << 2;
        float4 v = *reinterpret_cast<const float4*>(
            in_seq + (size_t)(row0 + row) * PP + off);
        __half2 a = __floats2half2_rn(v.x, v.y), b = __floats2half2_rn(v.z, v.w);
        uint2 u = { *reinterpret_cast<unsigned*>(&a), *reinterpret_cast<unsigned*>(&b) };
        *reinterpret_cast<uint2*>(&sA[row * 136 + off]) = u;
    }

    // ez1 (in16 -> zQ); chain ez2 s0 -> slot0
    {   float acc[2][2][4];
        gemm64<64, 128, 2, 0>(g_w16 + W_EZ1, sA, sB, acc, [&](int){
            issueB<64, 64>(g_w16 + W_EZ2, 0, 0, bB);
        });
        epi_to_smem<64, 2>(acc, bz1, zQ);
    }
    // ez2 (zQ -> zQ); chain ez3 s0 -> slot1
    {   float acc[2][2][4];
        gemm64<64, 64, 2, 0>(g_w16 + W_EZ2, zQ, sB, acc, [&](int){
            issueB<64, 64>(g_w16 + W_EZ3, 0, 1, bB);
        });
        __syncthreads();
        epi_to_smem<64, 2>(acc, bz2, zQ);
    }
    // ez3 (slot1) -> z_seq + Z init; chain ex1 s0 -> slot0
    {   float acc[2][2][4];
        gemm64<64, 64, 2, 1>(g_w16 + W_EZ3, zQ, sB, acc, [&](int){
            issueB<256, 128>(g_w16 + W_EX1, 0, 0, bB);
        });
        #pragma unroll
        for (int i = 0; i < 2; i++)
            #pragma unroll
            for (int h = 0; h < 2; h++) {
                const int row = wm * 32 + i * 16 + h * 8 + g;
                const int r = row0 + row;
                const int t = r & (TT - 1);
                const int rs = (t % 5 == 0) ? ((r >> 11) * CCH + t / 5) : -1;
                #pragma unroll
                for (int nt = 0; nt < 2; nt++) {
                    const int col = wn * 16 + nt * 8 + cq;
                    float v0 = ftanh(acc[i][nt][2 * h + 0] + __ldg(bz3 + col));
                    float v1 = ftanh(acc[i][nt][2 * h + 1] + __ldg(bz3 + col + 1));
                    *reinterpret_cast<float2*>(z_seq + (size_t)r * MM + col) =
                        make_float2(v0, v1);
                    if (rs >= 0)
                        *reinterpret_cast<float2*>(&g_Z[(size_t)rs * MM + col]) =
                            make_float2(v0, v1);
                }
            }
    }
    // ex1 (in16 -> in-place sA); chain ex2 s0 -> slot0
    {   float acc[2][8][4];
        gemm64<256, 128, 8, 0>(g_w16 + W_EX1, sA, sB, acc, [&](int){
            issueB<256, 256>(g_w16 + W_EX2, 0, 0, bB);
        });
        __syncthreads();
        epi_to_smem<256, 8>(acc, bx1, sA);
    }
    // ex2 (sA -> sA); chain ex3 s0 -> slot0
    {   float acc[2][8][4];
        gemm64<256, 256, 8, 0>(g_w16 + W_EX2, sA, sB, acc, [&](int){
            issueB<256, 256>(g_w16 + W_EX3, 0, 0, bB);
        });
        __syncthreads();
        epi_to_smem<256, 8>(acc, bx2, sA);
    }
    // ex3 -> xseq16 (gmem) + fp32 X init
    {   float acc[2][8][4];
        gemm64<256, 256, 8, 0>(g_w16 + W_EX3, sA, sB, acc, [](int){});
        #pragma unroll
        for (int i = 0; i < 2; i++)
            #pragma unroll
            for (int h = 0; h < 2; h++) {
                const int row = wm * 32 + i * 16 + h * 8 + g;
                const int r = row0 + row;
                const int t = r & (TT - 1);
                const int rs = (t % 5 == 0) ? ((r >> 11) * CCH + t / 5) : -1;
                #pragma unroll
                for (int nt = 0; nt < 8; nt++) {
                    const int col = wn * 64 + nt * 8 + cq;
                    float v0 = ftanh(acc[i][nt][2 * h + 0] + __ldg(bx3 + col));
                    float v1 = ftanh(acc[i][nt][2 * h + 1] + __ldg(bx3 + col + 1));
                    __half2 hv = __floats2half2_rn(v0, v1);
                    *reinterpret_cast<__half2*>(&g_xseq16[(size_t)r * KK + col]) = hv;
                    if (rs >= 0)
                        *reinterpret_cast<float2*>(&g_X[(size_t)rs * KK + col]) =
                            make_float2(v0, v1);
                }
            }
    }
}

// ---------------------------------------------------------------------------
// mega_dec: blocks [0, NMEGA) run the 5-step recurrence (FFMA-bound);
// blocks [NMEGA, NMEGA + NROWS/64) run the x_rec decoder (tensor-bound).
// Independent data -> SM-level overlap of the two pipe profiles.
// ---------------------------------------------------------------------------
__global__ void __launch_bounds__(256, 2)
mega_dec(float* __restrict__ zpred,
         const float* __restrict__ bd1, const float* __restrict__ bd2,
         float* __restrict__ x_rec)
{
    extern __shared__ __half sm[];

    if (blockIdx.x >= NMEGA) {
        // ---------------- x_rec decoder tile ----------------
        __half* sA = sm;
        __half* sB = sm + 16896;
        const uint32_t bB = (uint32_t)__cvta_generic_to_shared(sB);
        const int row0 = (blockIdx.x - NMEGA) * 64;
        dec_load(g_xseq16 + (size_t)row0 * KK, sA, bB);
        dec_body<0>(sA, sB, bB, bd1, bd2, x_rec, row0, 0);
        return;
    }

    // ---------------- recurrence (4 rows/warp, 8 warps) ----------------
    float* sP = reinterpret_cast<float*>(sm);            // P_TOT floats
    float* stzB = sP + P_TOT;                            // 8*4*68 floats

    const int tid = threadIdx.x;
    for (int i = tid; i < P_TOT; i += 256) sP[i] = g_step[i];
    __syncthreads();
    const float*  sWzT = sP + P_WZT;
    const float*  sAzQ = sP + P_AZT;
    const float4* sL4  = (const float4*)(sP + P_L);
    const float*  sRT  = sP + P_RT;
    const float*  sAzb = sP + P_AZB;

    const int w = tid >> 5, lane = tid & 31;
    float* stz = stzB + w * 4 * 68;
    const int r0 = (blockIdx.x * 8 + w) * 4;
    const int gr = lane >> 3, gq = lane & 7;

    int tbase[4]; size_t zoff[4];
    float zv0[4], zv1[4], xv[4][8];
    #pragma unroll
    for (int r = 0; r < 4; r++) {
        const int rr = r0 + r;
        const int b = rr / CCH, c = rr % CCH;
        tbase[r] = 5 * c;
        zoff[r]  = ((size_t)b * TT) * MM;
        zv0[r] = g_Z[(size_t)rr * MM + lane];
        zv1[r] = g_Z[(size_t)rr * MM + 32 + lane];
        #pragma unroll
        for (int k = 0; k < 8; k++)
            xv[r][k] = g_X[(size_t)rr * KK + lane + 32 * k];
    }

    #pragma unroll 1
    for (int s = 0; s < 5; s++) {
        #pragma unroll
        for (int r = 0; r < 4; r++) {
            stz[r * 68 + lane]      = htanh(zv0[r]);
            stz[r * 68 + 32 + lane] = htanh(zv1[r]);
        }
        __syncwarp();
        float a0[4] = {0.f,0.f,0.f,0.f}, a1[4] = {0.f,0.f,0.f,0.f};
        #pragma unroll
        for (int i4 = 0; i4 < 16; i4++) {
            float4 tz[4];
            #pragma unroll
            for (int r = 0; r < 4; r++)
                tz[r] = *(const float4*)&stz[r * 68 + i4 * 4];
            const float* wr = sWzT + (i4 * 4) * 64 + lane;
            #pragma unroll
            for (int ii = 0; ii < 4; ii++) {
                const float w0 = wr[ii * 64], w1 = wr[ii * 64 + 32];
                const float c0 = (ii == 0) ? tz[0].x : (ii == 1) ? tz[0].y
                               : (ii == 2) ? tz[0].z : tz[0].w;
                const float c1 = (ii == 0) ? tz[1].x : (ii == 1) ? tz[1].y
                               : (ii == 2) ? tz[1].z : tz[1].w;
                const float c2 = (ii == 0) ? tz[2].x : (ii == 1) ? tz[2].y
                               : (ii == 2) ? tz[2].z : tz[2].w;
                const float c3 = (ii == 0) ? tz[3].x : (ii == 1) ? tz[3].y
                               : (ii == 2) ? tz[3].z : tz[3].w;
                a0[0] = fmaf(c0, w0, a0[0]);  a1[0] = fmaf(c0, w1, a1[0]);
                a0[1] = fmaf(c1, w0, a0[1]);  a1[1] = fmaf(c1, w1, a1[1]);
                a0[2] = fmaf(c2, w0, a0[2]);  a1[2] = fmaf(c2, w1, a1[2]);
                a0[3] = fmaf(c3, w0, a0[3]);  a1[3] = fmaf(c3, w1, a1[3]);
            }
        }
        #pragma unroll
        for (int r = 0; r < 4; r++) {
            zv0[r] = zv0[r] + (a0[r] - zv0[r]) * 0.01f;
            zv1[r] = zv1[r] + (a1[r] - zv1[r]) * 0.01f;
        }
        __syncwarp();
        #pragma unroll
        for (int r = 0; r < 4; r++) {
            stz[r * 68 + lane]      = zv0[r];
            stz[r * 68 + 32 + lane] = zv1[r];
        }
        __syncwarp();
        float ga = 0.f;
        {
            const float4* az4 = (const float4*)(sAzQ + gq * 68);
            const float4* zz4 = (const float4*)&stz[gr * 68];
            #pragma unroll
            for (int i4 = 0; i4 < 16; i4++) {
                float4 a = az4[i4], z = zz4[i4];
                ga = fmaf(z.x, a.x, ga);
                ga = fmaf(z.y, a.y, ga);
                ga = fmaf(z.z, a.z, ga);
                ga = fmaf(z.w, a.w, ga);
            }
        }
        const float sg = 1.f / (1.f + __expf(-(ga + sAzb[gq])));
        float gu[4][8];
        #pragma unroll
        for (int r = 0; r < 4; r++)
            #pragma unroll
            for (int q = 0; q < 8; q++) gu[r][q] = 0.f;
        #pragma unroll
        for (int k = 0; k < 8; k++) {
            const int j = lane + 32 * k;
            const float4 l0 = sL4[j * 3], l1 = sL4[j * 3 + 1];
            #pragma unroll
            for (int r = 0; r < 4; r++) {
                const float tx = htanh(xv[r][k]);
                gu[r][0] = fmaf(tx, l0.x, gu[r][0]);
                gu[r][1] = fmaf(tx, l0.y, gu[r][1]);
                gu[r][2] = fmaf(tx, l0.z, gu[r][2]);
                gu[r][3] = fmaf(tx, l0.w, gu[r][3]);
                gu[r][4] = fmaf(tx, l1.x, gu[r][4]);
                gu[r][5] = fmaf(tx, l1.y, gu[r][5]);
                gu[r][6] = fmaf(tx, l1.z, gu[r][6]);
                gu[r][7] = fmaf(tx, l1.w, gu[r][7]);
            }
        }
        #pragma unroll
        for (int off = 16; off > 0; off >>= 1)
            #pragma unroll
            for (int r = 0; r < 4; r++)
                #pragma unroll
                for (int q = 0; q < 8; q++)
                    gu[r][q] += __shfl_xor_sync(0xffffffffu, gu[r][q], off);
        #pragma unroll
        for (int r = 0; r < 4; r++)
            #pragma unroll
            for (int q = 0; q < 8; q++)
                gu[r][q] *= __shfl_sync(0xffffffffu, sg, r * 8 + q);
        #pragma unroll
        for (int k = 0; k < 8; k++) {
            const int j = lane + 32 * k;
            float acc[4] = {0.f,0.f,0.f,0.f};
            #pragma unroll
            for (int q = 0; q < 8; q++) {
                const float wv = sRT[q * 256 + j];
                acc[0] = fmaf(gu[0][q], wv, acc[0]);
                acc[1] = fmaf(gu[1][q], wv, acc[1]);
                acc[2] = fmaf(gu[2][q], wv, acc[2]);
                acc[3] = fmaf(gu[3][q], wv, acc[3]);
            }
            #pragma unroll
            for (int r = 0; r < 4; r++)
                xv[r][k] = xv[r][k] + (acc[r] - xv[r][k]) * 0.01f;
        }
        #pragma unroll
        for (int r = 0; r < 4; r++) {
            const int t = tbase[r] + s;
            if (t < TT) {
                float* zp = zpred + zoff[r] + (size_t)t * MM;
                zp[lane]      = zv0[r];
                zp[lane + 32] = zv1[r];
            }
            __half* xd = g_X16s + ((size_t)s * NRP + (r0 + r)) * KK;
            #pragma unroll
            for (int k = 0; k < 8; k++)
                xd[lane + 32 * k] = __float2half(xv[r][k]);
        }
    }
}

// ---------------------------------------------------------------------------
// fused_dec (256 thr, BM=64, 2 CTAs/SM): X16s -> de1 -> de2 -> x_pred scatter
// ---------------------------------------------------------------------------
__global__ void __launch_bounds__(256, 2)
fused_dec(const float* __restrict__ bd1, const float* __restrict__ bd2,
          float* __restrict__ x_pred)
{
    extern __shared__ __half sm[];
    __half* sA = sm;
    __half* sB = sm + 16896;
    const uint32_t bB = (uint32_t)__cvta_generic_to_shared(sB);
    const int s    = blockIdx.x / (NRP / 64);
    const int row0 = (blockIdx.x % (NRP / 64)) * 64;
    dec_load(g_X16s + ((size_t)s * NRP + row0) * KK, sA, bB);
    dec_body<1>(sA, sB, bB, bd1, bd2, x_pred, row0, s);
}

// ---------------------------------------------------------------------------
extern "C" void kernel_launch(void* const* d_in, const int* in_sizes, int n_in,
                              void* d_out, int out_size)
{
    (void)in_sizes; (void)n_in; (void)out_size;
    const float* in_seq = (const float*)d_in[0];
    const float* L      = (const float*)d_in[1];
    const float* Rm     = (const float*)d_in[2];
    const float* Wz     = (const float*)d_in[3];
    const float* Az_w   = (const float*)d_in[4];
    const float* Az_b   = (const float*)d_in[5];
    const float* ex1_w  = (const float*)d_in[6];
    const float* ex1_b  = (const float*)d_in[7];
    const float* ex2_w  = (const float*)d_in[8];
    const float* ex2_b  = (const float*)d_in[9];
    const float* ex3_w  = (const float*)d_in[10];
    const float* ex3_b  = (const float*)d_in[11];
    const float* ez1_w  = (const float*)d_in[12];
    const float* ez1_b  = (const float*)d_in[13];
    const float* ez2_w  = (const float*)d_in[14];
    const float* ez2_b  = (const float*)d_in[15];
    const float* ez3_w  = (const float*)d_in[16];
    const float* ez3_b  = (const float*)d_in[17];
    const float* de1_w  = (const float*)d_in[18];
    const float* de1_b  = (const float*)d_in[19];
    const float* de2_w  = (const float*)d_in[20];
    const float* de2_b  = (const float*)d_in[21];

    float* out    = (float*)d_out;
    float* x_pred = out;
    float* x_rec  = out + (size_t)BB*TT*PP;
    float* z_pred = out + 2*(size_t)BB*TT*PP;
    float* z_seq  = z_pred + (size_t)BB*TT*MM;

    const int SMF = (16896 + 36864) * 2;   // 107520 B -> 2 CTAs/SM
    cudaFuncSetAttribute(fused_xz_enc, cudaFuncAttributeMaxDynamicSharedMemorySize, SMF);
    cudaFuncSetAttribute(mega_dec,     cudaFuncAttributeMaxDynamicSharedMemorySize, SMF);
    cudaFuncSetAttribute(fused_dec,    cudaFuncAttributeMaxDynamicSharedMemorySize, SMF);

    // 1. weight conversions + step-weight pack (small)
    {
        const int TOT = W_TOTAL/4 + P_TOT;
        conv_kernel<<<(TOT + 255) / 256, 256>>>(ex1_w, ex2_w, ex3_w,
                                                ez1_w, ez2_w, ez3_w, de1_w, de2_w,
                                                Wz, Az_w, Az_b, L, Rm);
    }

    // 2. encoders (x + z) — seeds scan state, writes xseq16
    fused_xz_enc<<<NROWS/64, 256, SMF>>>(in_seq,
                                         ex1_b, ex2_b, ex3_b,
                                         ez1_b, ez2_b, ez3_b, z_seq);

    // 3. recurrence + x_rec decoder co-scheduled in one launch
    mega_dec<<<NMEGA + NROWS/64, 256, SMF>>>(z_pred, de1_b, de2_b, x_rec);

    // 4. x_pred decoder over all 5 step snapshots
    fused_dec<<<5 * (NRP/64), 256, SMF>>>(de1_b, de2_b, x_pred);
}